// round 9
// baseline (speedup 1.0000x reference)
#include <cuda_runtime.h>
#include <cuda_bf16.h>

// Problem constants (fixed by the reference).
#define N_  512
#define L_  5
#define H_  8
#define D_  16
#define E_  10000

// Scratch: projected edge table P[e][l][h] = dot(edge_features[e], W[1+l][h]).
// E*L*H = 400,000 floats = 1.6 MB (L2-resident). Row stride per e = 40 floats
// = 160 B. Chunk (e,l) = 32 B at offset e*160 + l*32; since 160 ≡ 32 (mod 128),
// every chunk is 32B-aligned inside a single 128B line (never straddles).
__device__ float g_P[E_ * L_ * H_];

// ---------------------------------------------------------------------------
// Kernel 1: projection. One thread per (e, l): 8 dots of length 16.
// 50,000 threads. W rows 1..L staged in smem (uniform broadcast reads).
// ---------------------------------------------------------------------------
__global__ void __launch_bounds__(256)
project_kernel(const float* __restrict__ F,   // [E, D]
               const float* __restrict__ W)   // [L+1, H*D]
{
    __shared__ float sW[L_ * H_ * D_];        // 640 floats, rows 1..L
    for (int i = threadIdx.x; i < L_ * H_ * D_; i += blockDim.x)
        sW[i] = W[H_ * D_ + i];               // skip row 0
    __syncthreads();

    int idx = blockIdx.x * blockDim.x + threadIdx.x;
    if (idx >= E_ * L_) return;
    int e = idx / L_;
    int l = idx - e * L_;

    // Load the 16-float feature row (4x float4). Five threads share a row ->
    // L1-hit for 4 of them.
    const float4* fp = reinterpret_cast<const float4*>(F + (size_t)e * D_);
    float4 f0 = fp[0], f1 = fp[1], f2 = fp[2], f3 = fp[3];
    float fr[D_] = { f0.x, f0.y, f0.z, f0.w,
                     f1.x, f1.y, f1.z, f1.w,
                     f2.x, f2.y, f2.z, f2.w,
                     f3.x, f3.y, f3.z, f3.w };

    float out[H_];
    #pragma unroll
    for (int h = 0; h < H_; ++h) {
        float acc = 0.0f;
        const float* w = &sW[(l * H_ + h) * D_];
        #pragma unroll
        for (int d = 0; d < D_; ++d)
            acc = fmaf(fr[d], w[d], acc);
        out[h] = acc;
    }

    // 8 floats = 2 float4 stores at byte offset e*160 + l*32 (16B-aligned).
    float4* dst = reinterpret_cast<float4*>(g_P + (size_t)e * (L_ * H_) + l * H_);
    float4 v0 = { out[0], out[1], out[2], out[3] };
    float4 v1 = { out[4], out[5], out[6], out[7] };
    dst[0] = v0;
    dst[1] = v1;
}

// ---------------------------------------------------------------------------
// Kernel 2: gather/average. TWO lanes per pair (lane c handles float4 chunk c
// of each 32B P-row chunk) so both lanes hit the SAME 128B line -> one L1
// wavefront serves one (pair,l) gather instead of two. Block = 256 threads
// = 128 pairs.
//
// Indices arrive as int32 (harness dtype map has no int64). Index outside
// [0,E) => invalid/skip (== clip+mask in the reference). Divisor =
// max(valid_count, 1).
// ---------------------------------------------------------------------------
#define PAIRS_PER_BLK 128

__global__ void __launch_bounds__(256)
gather_kernel(const int* __restrict__ spe,   // [N, N, L] int32
              float* __restrict__ out)       // [H, N, N]
{
    __shared__ int   s_idx[PAIRS_PER_BLK * L_];     // 640 ints
    __shared__ float s_out[H_ * 129];               // padded stride vs bank conflicts

    const int base = blockIdx.x * PAIRS_PER_BLK;    // first pair of this block
    const int tid  = threadIdx.x;

    // Coalesced index staging: 640 ints = 160 int4 loads (base*L_*4 bytes is
    // 16B-aligned since 128*5*4 = 2560).
    const int4* g4 = reinterpret_cast<const int4*>(spe + (size_t)base * L_);
    if (tid < (PAIRS_PER_BLK * L_) / 4)
        reinterpret_cast<int4*>(s_idx)[tid] = g4[tid];
    __syncthreads();

    const int pair = tid >> 1;      // 0..127
    const int c    = tid & 1;       // float4 chunk within the 32B row chunk

    float a0 = 0.f, a1 = 0.f, a2 = 0.f, a3 = 0.f;
    int cnt = 0;

    #pragma unroll
    for (int l = 0; l < L_; ++l) {
        int e = s_idx[pair * L_ + l];               // broadcast to both lanes
        if ((unsigned)e < (unsigned)E_) {
            ++cnt;
            const float4* src = reinterpret_cast<const float4*>(
                g_P + (size_t)e * (L_ * H_) + l * H_ + c * 4);
            float4 v = *src;
            a0 += v.x; a1 += v.y; a2 += v.z; a3 += v.w;
        }
    }

    float inv = 1.0f / (float)(cnt > 0 ? cnt : 1);

    // Lane c owns heads c*4 .. c*4+3. Stage to smem for coalesced plane writes.
    const int hb = c * 4;
    s_out[(hb + 0) * 129 + pair] = a0 * inv;
    s_out[(hb + 1) * 129 + pair] = a1 * inv;
    s_out[(hb + 2) * 129 + pair] = a2 * inv;
    s_out[(hb + 3) * 129 + pair] = a3 * inv;
    __syncthreads();

    // 8 planes x 128 pairs, fully coalesced (512B contiguous per plane seg).
    const int NN = N_ * N_;
    #pragma unroll
    for (int k = 0; k < (H_ * PAIRS_PER_BLK) / 256; ++k) {
        int i = k * 256 + tid;
        int h = i >> 7;           // /128
        int j = i & 127;          // %128
        out[h * NN + base + j] = s_out[h * 129 + j];
    }
}

// ---------------------------------------------------------------------------
// Launch: inputs in metadata order:
//   d_in[0] = edge_features_s      float32 [E*D]
//   d_in[1] = edge_weights         float32 [(L+1)*H*D]
//   d_in[2] = shortest_path_edges  int32   [N*N*L]
// d_out = float32 [H*N*N]
// ---------------------------------------------------------------------------
extern "C" void kernel_launch(void* const* d_in, const int* in_sizes, int n_in,
                              void* d_out, int out_size)
{
    const float* F   = (const float*)d_in[0];
    const float* W   = (const float*)d_in[1];
    const int*   spe = (const int*)d_in[2];
    float*       out = (float*)d_out;

    project_kernel<<<(E_ * L_ + 255) / 256, 256>>>(F, W);
    gather_kernel<<<(N_ * N_) / PAIRS_PER_BLK, 256>>>(spe, out);
}

// round 10
// speedup vs baseline: 1.0477x; 1.0477x over previous
#include <cuda_runtime.h>
#include <cuda_bf16.h>

// Problem constants (fixed by the reference).
#define N_  512
#define L_  5
#define H_  8
#define D_  16
#define E_  10000

// Scratch: projected edge table P[e][l][h] = dot(edge_features[e], W[1+l][h]).
// E*L*H = 400,000 floats = 1.6 MB (L2-resident). Row stride per e = 40 floats
// = 160 B. Chunk (e,l) = 32 B at offset e*160 + l*32; since 160 ≡ 32 (mod 128),
// every chunk is 32B-aligned inside a single 128B line (never straddles).
__device__ float g_P[E_ * L_ * H_];

// ---------------------------------------------------------------------------
// Kernel 1: projection. One thread per (e, l): 8 dots of length 16.
// 50,000 threads. W rows 1..L staged in smem (uniform broadcast reads).
// ---------------------------------------------------------------------------
__global__ void __launch_bounds__(256)
project_kernel(const float* __restrict__ F,   // [E, D]
               const float* __restrict__ W)   // [L+1, H*D]
{
    __shared__ float sW[L_ * H_ * D_];        // 640 floats, rows 1..L
    for (int i = threadIdx.x; i < L_ * H_ * D_; i += blockDim.x)
        sW[i] = W[H_ * D_ + i];               // skip row 0
    __syncthreads();

    int idx = blockIdx.x * blockDim.x + threadIdx.x;
    if (idx >= E_ * L_) return;
    int e = idx / L_;
    int l = idx - e * L_;

    const float4* fp = reinterpret_cast<const float4*>(F + (size_t)e * D_);
    float4 f0 = fp[0], f1 = fp[1], f2 = fp[2], f3 = fp[3];
    float fr[D_] = { f0.x, f0.y, f0.z, f0.w,
                     f1.x, f1.y, f1.z, f1.w,
                     f2.x, f2.y, f2.z, f2.w,
                     f3.x, f3.y, f3.z, f3.w };

    float out[H_];
    #pragma unroll
    for (int h = 0; h < H_; ++h) {
        float acc = 0.0f;
        const float* w = &sW[(l * H_ + h) * D_];
        #pragma unroll
        for (int d = 0; d < D_; ++d)
            acc = fmaf(fr[d], w[d], acc);
        out[h] = acc;
    }

    float4* dst = reinterpret_cast<float4*>(g_P + (size_t)e * (L_ * H_) + l * H_);
    float4 v0 = { out[0], out[1], out[2], out[3] };
    float4 v1 = { out[4], out[5], out[6], out[7] };
    dst[0] = v0;
    dst[1] = v1;
}

// ---------------------------------------------------------------------------
// Kernel 2: gather/average. 256 threads handle 256 pairs: thread-pair
// (2 lanes) per output pair, lane c loads float4 chunk c of each 32B P-row
// chunk (both lanes hit the SAME 128B line -> one L1 wavefront per gather),
// and each thread-pair covers TWO pairs (pair_local, pair_local+128) so a
// thread keeps 10 independent LDG.128 in flight (latency hiding via ILP).
// Gathers are BRANCHLESS: invalid index (-1) -> load row 0 (hot line) and
// accumulate with mask 0. Divisor = max(valid_count, 1).
//
// Indices arrive as int32 (harness dtype map has no int64).
// ---------------------------------------------------------------------------
#define PAIRS_PER_BLK 256

__global__ void __launch_bounds__(256)
gather_kernel(const int* __restrict__ spe,   // [N, N, L] int32
              float* __restrict__ out)       // [H, N, N]
{
    __shared__ int   s_idx[PAIRS_PER_BLK * L_];   // 1280 ints
    __shared__ float s_out[H_ * (PAIRS_PER_BLK + 1)];

    const int base = blockIdx.x * PAIRS_PER_BLK;
    const int tid  = threadIdx.x;

    // Coalesced index staging: 1280 ints = 320 int4 (base*5*4 B is 16B-aligned:
    // 256*5*4 = 5120).
    const int4* g4 = reinterpret_cast<const int4*>(spe + (size_t)base * L_);
    #pragma unroll
    for (int i = tid; i < (PAIRS_PER_BLK * L_) / 4; i += 256)
        reinterpret_cast<int4*>(s_idx)[i] = g4[i];
    __syncthreads();

    const int pair = tid >> 1;      // 0..127
    const int c    = tid & 1;       // float4 chunk within the 32B row chunk
    const int coff = c * 4;

    float a[2][4];
    float cntf[2];
    #pragma unroll
    for (int pp = 0; pp < 2; ++pp) {
        a[pp][0] = a[pp][1] = a[pp][2] = a[pp][3] = 0.f;
        cntf[pp] = 0.f;
    }

    #pragma unroll
    for (int pp = 0; pp < 2; ++pp) {
        const int pr = pair + pp * 128;
        #pragma unroll
        for (int l = 0; l < L_; ++l) {
            int e = s_idx[pr * L_ + l];
            bool valid = (unsigned)e < (unsigned)E_;
            int  ei    = valid ? e : 0;
            float m    = valid ? 1.0f : 0.0f;
            const float4 v = *reinterpret_cast<const float4*>(
                g_P + (size_t)ei * (L_ * H_) + l * H_ + coff);
            a[pp][0] = fmaf(m, v.x, a[pp][0]);
            a[pp][1] = fmaf(m, v.y, a[pp][1]);
            a[pp][2] = fmaf(m, v.z, a[pp][2]);
            a[pp][3] = fmaf(m, v.w, a[pp][3]);
            cntf[pp] += m;
        }
    }

    #pragma unroll
    for (int pp = 0; pp < 2; ++pp) {
        const int pr  = pair + pp * 128;
        float inv = 1.0f / fmaxf(cntf[pp], 1.0f);
        s_out[(coff + 0) * (PAIRS_PER_BLK + 1) + pr] = a[pp][0] * inv;
        s_out[(coff + 1) * (PAIRS_PER_BLK + 1) + pr] = a[pp][1] * inv;
        s_out[(coff + 2) * (PAIRS_PER_BLK + 1) + pr] = a[pp][2] * inv;
        s_out[(coff + 3) * (PAIRS_PER_BLK + 1) + pr] = a[pp][3] * inv;
    }
    __syncthreads();

    // 8 planes x 256 pairs, fully coalesced (1KB contiguous per plane seg).
    const int NN = N_ * N_;
    #pragma unroll
    for (int k = 0; k < (H_ * PAIRS_PER_BLK) / 256; ++k) {
        int i = k * 256 + tid;
        int h = i >> 8;            // /256
        int j = i & 255;           // %256
        out[h * NN + base + j] = s_out[h * (PAIRS_PER_BLK + 1) + j];
    }
}

// ---------------------------------------------------------------------------
// Launch: inputs in metadata order:
//   d_in[0] = edge_features_s      float32 [E*D]
//   d_in[1] = edge_weights         float32 [(L+1)*H*D]
//   d_in[2] = shortest_path_edges  int32   [N*N*L]
// d_out = float32 [H*N*N]
// ---------------------------------------------------------------------------
extern "C" void kernel_launch(void* const* d_in, const int* in_sizes, int n_in,
                              void* d_out, int out_size)
{
    const float* F   = (const float*)d_in[0];
    const float* W   = (const float*)d_in[1];
    const int*   spe = (const int*)d_in[2];
    float*       out = (float*)d_out;

    project_kernel<<<(E_ * L_ + 255) / 256, 256>>>(F, W);
    gather_kernel<<<(N_ * N_) / PAIRS_PER_BLK, 256>>>(spe, out);
}

// round 11
// speedup vs baseline: 1.1996x; 1.1450x over previous
#include <cuda_runtime.h>
#include <cuda_bf16.h>

// Problem constants (fixed by the reference).
#define N_  512
#define L_  5
#define H_  8
#define D_  16
#define E_  10000

// Scratch: projected edge table P[e][l][h] = dot(edge_features[e], W[1+l][h]).
// E*L*H = 400,000 floats = 1.6 MB (L2-resident). Row stride per e = 40 floats
// = 160 B. Chunk (e,l) = 32 B at offset e*160 + l*32; since 160 ≡ 32 (mod 128),
// every chunk is 32B-aligned inside a single 128B line (never straddles).
__device__ float g_P[E_ * L_ * H_];

// ---------------------------------------------------------------------------
// Kernel 1: projection (R7 form — empirically the fastest config).
// One thread per edge e computes all 40 (l,h) dots. W rows 1..L in smem.
// ---------------------------------------------------------------------------
__global__ void __launch_bounds__(128)
project_kernel(const float* __restrict__ F,   // [E, D]
               const float* __restrict__ W)   // [L+1, H*D]
{
    __shared__ float sW[L_ * H_ * D_];        // 640 floats, rows 1..L
    for (int i = threadIdx.x; i < L_ * H_ * D_; i += blockDim.x)
        sW[i] = W[H_ * D_ + i];               // skip row 0
    __syncthreads();

    int e = blockIdx.x * blockDim.x + threadIdx.x;
    if (e >= E_) return;

    const float4* fp = reinterpret_cast<const float4*>(F + (size_t)e * D_);
    float4 f0 = fp[0], f1 = fp[1], f2 = fp[2], f3 = fp[3];
    float fr[D_] = { f0.x, f0.y, f0.z, f0.w,
                     f1.x, f1.y, f1.z, f1.w,
                     f2.x, f2.y, f2.z, f2.w,
                     f3.x, f3.y, f3.z, f3.w };

    float out[L_ * H_];
    #pragma unroll
    for (int l = 0; l < L_; ++l) {
        #pragma unroll
        for (int h = 0; h < H_; ++h) {
            float acc = 0.0f;
            const float* w = &sW[(l * H_ + h) * D_];
            #pragma unroll
            for (int d = 0; d < D_; ++d)
                acc = fmaf(fr[d], w[d], acc);
            out[l * H_ + h] = acc;
        }
    }

    float4* dst = reinterpret_cast<float4*>(g_P + (size_t)e * (L_ * H_));
    #pragma unroll
    for (int i = 0; i < (L_ * H_) / 4; ++i) {
        float4 v = { out[4*i], out[4*i+1], out[4*i+2], out[4*i+3] };
        dst[i] = v;
    }
}

// ---------------------------------------------------------------------------
// Kernel 2: gather/average. Thread-pair (2 lanes) per output pair: lane c
// loads float4 chunk c of each 32B P-row chunk, so both lanes hit the SAME
// 128B line -> one L1 wavefront per (pair,l) gather. Each thread-pair covers
// FOUR pairs (pr = pair + pp*128, pp=0..3) -> 20 independent LDG.128 in
// flight per thread, saturating the L1tex wavefront pipe (the R10 binder:
// 0.47 wf/cycle at MLP=10).
// Branchless: invalid index (-1) loads row 0 (hot line), mask-accumulated.
// Divisor = max(valid_count, 1). Indices arrive as int32.
// ---------------------------------------------------------------------------
#define PAIRS_PER_BLK 512
#define PP_           4

__global__ void __launch_bounds__(256)
gather_kernel(const int* __restrict__ spe,   // [N, N, L] int32
              float* __restrict__ out)       // [H, N, N]
{
    __shared__ int   s_idx[PAIRS_PER_BLK * L_];        // 2560 ints = 10 KB
    __shared__ float s_out[H_ * (PAIRS_PER_BLK + 1)];  // ~16 KB, padded stride

    const int base = blockIdx.x * PAIRS_PER_BLK;
    const int tid  = threadIdx.x;

    // Coalesced index staging: 2560 ints = 640 int4 (base*5*4 = blockIdx*10240
    // bytes, 16B-aligned).
    const int4* g4 = reinterpret_cast<const int4*>(spe + (size_t)base * L_);
    #pragma unroll
    for (int i = tid; i < (PAIRS_PER_BLK * L_) / 4; i += 256)
        reinterpret_cast<int4*>(s_idx)[i] = g4[i];
    __syncthreads();

    const int pair = tid >> 1;      // 0..127
    const int c    = tid & 1;       // float4 chunk within the 32B row chunk
    const int coff = c * 4;

    float a[PP_][4];
    float cntf[PP_];
    #pragma unroll
    for (int pp = 0; pp < PP_; ++pp) {
        a[pp][0] = a[pp][1] = a[pp][2] = a[pp][3] = 0.f;
        cntf[pp] = 0.f;
    }

    #pragma unroll
    for (int pp = 0; pp < PP_; ++pp) {
        const int pr = pair + pp * 128;
        #pragma unroll
        for (int l = 0; l < L_; ++l) {
            int e = s_idx[pr * L_ + l];
            bool valid = (unsigned)e < (unsigned)E_;
            int  ei    = valid ? e : 0;
            float m    = valid ? 1.0f : 0.0f;
            const float4 v = *reinterpret_cast<const float4*>(
                g_P + (size_t)ei * (L_ * H_) + l * H_ + coff);
            a[pp][0] = fmaf(m, v.x, a[pp][0]);
            a[pp][1] = fmaf(m, v.y, a[pp][1]);
            a[pp][2] = fmaf(m, v.z, a[pp][2]);
            a[pp][3] = fmaf(m, v.w, a[pp][3]);
            cntf[pp] += m;
        }
    }

    #pragma unroll
    for (int pp = 0; pp < PP_; ++pp) {
        const int pr  = pair + pp * 128;
        float inv = 1.0f / fmaxf(cntf[pp], 1.0f);
        s_out[(coff + 0) * (PAIRS_PER_BLK + 1) + pr] = a[pp][0] * inv;
        s_out[(coff + 1) * (PAIRS_PER_BLK + 1) + pr] = a[pp][1] * inv;
        s_out[(coff + 2) * (PAIRS_PER_BLK + 1) + pr] = a[pp][2] * inv;
        s_out[(coff + 3) * (PAIRS_PER_BLK + 1) + pr] = a[pp][3] * inv;
    }
    __syncthreads();

    // 8 planes x 512 pairs, fully coalesced (2KB contiguous per plane seg).
    const int NN = N_ * N_;
    #pragma unroll
    for (int k = 0; k < (H_ * PAIRS_PER_BLK) / 256; ++k) {
        int i = k * 256 + tid;
        int h = i >> 9;            // /512
        int j = i & 511;           // %512
        out[h * NN + base + j] = s_out[h * (PAIRS_PER_BLK + 1) + j];
    }
}

// ---------------------------------------------------------------------------
// Launch: inputs in metadata order:
//   d_in[0] = edge_features_s      float32 [E*D]
//   d_in[1] = edge_weights         float32 [(L+1)*H*D]
//   d_in[2] = shortest_path_edges  int32   [N*N*L]
// d_out = float32 [H*N*N]
// ---------------------------------------------------------------------------
extern "C" void kernel_launch(void* const* d_in, const int* in_sizes, int n_in,
                              void* d_out, int out_size)
{
    const float* F   = (const float*)d_in[0];
    const float* W   = (const float*)d_in[1];
    const int*   spe = (const int*)d_in[2];
    float*       out = (float*)d_out;

    project_kernel<<<(E_ + 127) / 128, 128>>>(F, W);
    gather_kernel<<<(N_ * N_) / PAIRS_PER_BLK, 256>>>(spe, out);
}

// round 12
// speedup vs baseline: 1.2417x; 1.0351x over previous
#include <cuda_runtime.h>
#include <cuda_bf16.h>

// Problem constants (fixed by the reference).
#define N_  512
#define L_  5
#define H_  8
#define D_  16
#define E_  10000

// Scratch: projected edge table P[e][l][h] = dot(edge_features[e], W[1+l][h]).
// E*L*H = 400,000 floats = 1.6 MB (L2-resident). Row stride per e = 40 floats
// = 160 B. Chunk (e,l) = 32 B at offset e*160 + l*32; since 160 ≡ 32 (mod 128),
// every chunk is 32B-aligned inside a single 128B line (never straddles).
__device__ float g_P[E_ * L_ * H_];

// ---------------------------------------------------------------------------
// Kernel 1: projection (R7 form — empirically the fastest config).
// One thread per edge e computes all 40 (l,h) dots. W rows 1..L in smem.
// ---------------------------------------------------------------------------
__global__ void __launch_bounds__(128)
project_kernel(const float* __restrict__ F,   // [E, D]
               const float* __restrict__ W)   // [L+1, H*D]
{
    __shared__ float sW[L_ * H_ * D_];        // 640 floats, rows 1..L
    for (int i = threadIdx.x; i < L_ * H_ * D_; i += blockDim.x)
        sW[i] = W[H_ * D_ + i];               // skip row 0
    __syncthreads();

    int e = blockIdx.x * blockDim.x + threadIdx.x;
    if (e >= E_) return;

    const float4* fp = reinterpret_cast<const float4*>(F + (size_t)e * D_);
    float4 f0 = fp[0], f1 = fp[1], f2 = fp[2], f3 = fp[3];
    float fr[D_] = { f0.x, f0.y, f0.z, f0.w,
                     f1.x, f1.y, f1.z, f1.w,
                     f2.x, f2.y, f2.z, f2.w,
                     f3.x, f3.y, f3.z, f3.w };

    float out[L_ * H_];
    #pragma unroll
    for (int l = 0; l < L_; ++l) {
        #pragma unroll
        for (int h = 0; h < H_; ++h) {
            float acc = 0.0f;
            const float* w = &sW[(l * H_ + h) * D_];
            #pragma unroll
            for (int d = 0; d < D_; ++d)
                acc = fmaf(fr[d], w[d], acc);
            out[l * H_ + h] = acc;
        }
    }

    float4* dst = reinterpret_cast<float4*>(g_P + (size_t)e * (L_ * H_));
    #pragma unroll
    for (int i = 0; i < (L_ * H_) / 4; ++i) {
        float4 v = { out[4*i], out[4*i+1], out[4*i+2], out[4*i+3] };
        dst[i] = v;
    }
}

// ---------------------------------------------------------------------------
// Kernel 2: gather/average.
// Proven per-thread shape (R10): thread-pair (2 lanes) per output pair, lane c
// loads float4 chunk c of each 32B P-row chunk -> both lanes hit the SAME
// 128B line -> one L1 wavefront per (pair,l) gather; PP=2 pairs per thread
// (10 independent LDG.128 in flight).
// R11 lesson: L1tex service tracks RESIDENT WARPS, not per-thread ILP.
// So: 128-thread blocks (64 thread-pairs x 2 pairs = 128 pairs/block),
// grid = 2048 -> ~14 blocks/SM, occupancy up from 68% toward ~90%.
// Branchless: invalid index (-1) loads row 0 (hot line), mask-accumulated.
// Divisor = max(valid_count, 1). Indices arrive as int32.
// ---------------------------------------------------------------------------
#define PAIRS_PER_BLK 128
#define THREADS_G     128
#define PP_           2

__global__ void __launch_bounds__(THREADS_G)
gather_kernel(const int* __restrict__ spe,   // [N, N, L] int32
              float* __restrict__ out)       // [H, N, N]
{
    __shared__ int   s_idx[PAIRS_PER_BLK * L_];        // 640 ints = 2.5 KB
    __shared__ float s_out[H_ * (PAIRS_PER_BLK + 1)];  // ~4 KB, padded stride

    const int base = blockIdx.x * PAIRS_PER_BLK;
    const int tid  = threadIdx.x;

    // Coalesced index staging: 640 ints = 160 int4 (base*5*4 = blockIdx*2560
    // bytes, 16B-aligned).
    const int4* g4 = reinterpret_cast<const int4*>(spe + (size_t)base * L_);
    for (int i = tid; i < (PAIRS_PER_BLK * L_) / 4; i += THREADS_G)
        reinterpret_cast<int4*>(s_idx)[i] = g4[i];
    __syncthreads();

    const int pair = tid >> 1;      // 0..63
    const int c    = tid & 1;       // float4 chunk within the 32B row chunk
    const int coff = c * 4;

    float a[PP_][4];
    float cntf[PP_];
    #pragma unroll
    for (int pp = 0; pp < PP_; ++pp) {
        a[pp][0] = a[pp][1] = a[pp][2] = a[pp][3] = 0.f;
        cntf[pp] = 0.f;
    }

    #pragma unroll
    for (int pp = 0; pp < PP_; ++pp) {
        const int pr = pair + pp * 64;
        #pragma unroll
        for (int l = 0; l < L_; ++l) {
            int e = s_idx[pr * L_ + l];
            bool valid = (unsigned)e < (unsigned)E_;
            int  ei    = valid ? e : 0;
            float m    = valid ? 1.0f : 0.0f;
            const float4 v = *reinterpret_cast<const float4*>(
                g_P + (size_t)ei * (L_ * H_) + l * H_ + coff);
            a[pp][0] = fmaf(m, v.x, a[pp][0]);
            a[pp][1] = fmaf(m, v.y, a[pp][1]);
            a[pp][2] = fmaf(m, v.z, a[pp][2]);
            a[pp][3] = fmaf(m, v.w, a[pp][3]);
            cntf[pp] += m;
        }
    }

    #pragma unroll
    for (int pp = 0; pp < PP_; ++pp) {
        const int pr  = pair + pp * 64;
        float inv = 1.0f / fmaxf(cntf[pp], 1.0f);
        s_out[(coff + 0) * (PAIRS_PER_BLK + 1) + pr] = a[pp][0] * inv;
        s_out[(coff + 1) * (PAIRS_PER_BLK + 1) + pr] = a[pp][1] * inv;
        s_out[(coff + 2) * (PAIRS_PER_BLK + 1) + pr] = a[pp][2] * inv;
        s_out[(coff + 3) * (PAIRS_PER_BLK + 1) + pr] = a[pp][3] * inv;
    }
    __syncthreads();

    // 8 planes x 128 pairs, fully coalesced (512B contiguous per plane seg).
    const int NN = N_ * N_;
    #pragma unroll
    for (int k = 0; k < (H_ * PAIRS_PER_BLK) / THREADS_G; ++k) {
        int i = k * THREADS_G + tid;
        int h = i >> 7;            // /128
        int j = i & 127;           // %128
        out[h * NN + base + j] = s_out[h * (PAIRS_PER_BLK + 1) + j];
    }
}

// ---------------------------------------------------------------------------
// Launch: inputs in metadata order:
//   d_in[0] = edge_features_s      float32 [E*D]
//   d_in[1] = edge_weights         float32 [(L+1)*H*D]
//   d_in[2] = shortest_path_edges  int32   [N*N*L]
// d_out = float32 [H*N*N]
// ---------------------------------------------------------------------------
extern "C" void kernel_launch(void* const* d_in, const int* in_sizes, int n_in,
                              void* d_out, int out_size)
{
    const float* F   = (const float*)d_in[0];
    const float* W   = (const float*)d_in[1];
    const int*   spe = (const int*)d_in[2];
    float*       out = (float*)d_out;

    project_kernel<<<(E_ + 127) / 128, 128>>>(F, W);
    gather_kernel<<<(N_ * N_) / PAIRS_PER_BLK, THREADS_G>>>(spe, out);
}